// round 11
// baseline (speedup 1.0000x reference)
#include <cuda_runtime.h>
#include <math.h>

#define BATCH 65536
#define WPB   4
#define TPB   128
#define H_ST  36
#define P_ST  36
#define X_ST  33
#define W1_ST 49
#define W2_ST 65
#define FULL  0xffffffffu

__global__ void __launch_bounds__(TPB, 3) kalman_kernel(
    const float* __restrict__ x_post, const float* __restrict__ P_post,
    const float* __restrict__ ctx,    const float* __restrict__ meas,
    const float* __restrict__ W1,     const float* __restrict__ b1,
    const float* __restrict__ W2,     const float* __restrict__ b2,
    const float* __restrict__ Hm,     const float* __restrict__ logQ,
    const float* __restrict__ logR,
    float* __restrict__ out_x, float* __restrict__ out_P)
{
    __shared__ __align__(16) float Hs[32 * H_ST];
    __shared__ __align__(16) union SU {
        struct { float W1s[64 * W1_ST]; float W2s[32 * W2_ST]; } m;  // MLP phase
        float xt[WPB][32 * X_ST];                                    // X = S^-1 M
    } u;
    __shared__ __align__(16) float Pt[WPB][32 * P_ST];   // P_pred rows (f32)
    __shared__ float b1s[64], b2s[32], eQs[32], eRs[32];
    __shared__ float mlpbuf[WPB][64];
    __shared__ float ybuf[WPB][32];

    const int tid = threadIdx.x;
    for (int i = tid; i < 64 * 48; i += TPB) u.m.W1s[(i / 48) * W1_ST + (i % 48)] = W1[i];
    for (int i = tid; i < 32 * 64; i += TPB) u.m.W2s[(i >> 6) * W2_ST + (i & 63)] = W2[i];
    for (int i = tid; i < 32 * 32; i += TPB) Hs[(i >> 5) * H_ST + (i & 31)] = Hm[i];
    if (tid < 64) b1s[tid] = b1[tid];
    if (tid < 32) {
        b2s[tid] = b2[tid];
        eQs[tid] = expf(logQ[tid]);
        eRs[tid] = expf(logR[tid]) + 1e-6f;
    }
    __syncthreads();

    const int w    = tid >> 5;
    const int lane = tid & 31;
    const int b    = blockIdx.x * WPB + w;
    float* tP = Pt[w];

    float hrow[32];
#pragma unroll
    for (int j = 0; j < 32; j++) hrow[j] = Hs[lane * H_ST + j];

    // ===================== MLP (f32, noise-benign) =====================
    mlpbuf[w][lane] = x_post[(size_t)b * 32 + lane];
    if (lane < 16) mlpbuf[w][32 + lane] = ctx[(size_t)b * 16 + lane];
    __syncwarp();

    float a0 = b1s[lane], a1 = b1s[lane + 32];
#pragma unroll
    for (int j = 0; j < 48; j++) {
        float vj = mlpbuf[w][j];
        a0 = fmaf(u.m.W1s[lane * W1_ST + j], vj, a0);
        a1 = fmaf(u.m.W1s[(lane + 32) * W1_ST + j], vj, a1);
    }
    float h0 = tanhf(a0), h1 = tanhf(a1);
    __syncwarp();
    mlpbuf[w][lane]      = h0;
    mlpbuf[w][lane + 32] = h1;
    __syncwarp();

    float xp = b2s[lane];
#pragma unroll
    for (int k = 0; k < 64; k++) xp = fmaf(u.m.W2s[lane * W2_ST + k], mlpbuf[w][k], xp);
    __syncwarp();
    mlpbuf[w][lane] = xp;
    __syncwarp();

    float yv = meas[(size_t)b * 32 + lane];
#pragma unroll
    for (int j = 0; j < 32; j++) yv = fmaf(-mlpbuf[w][j], hrow[j], yv);
    ybuf[w][lane] = yv;

    // All warps must finish W1/W2 reads before anyone writes the X overlay.
    __syncthreads();

    // ===== P_pred rows into shared (f32, matches reference storage) =====
    {
        const float4* Pr = (const float4*)(P_post + (size_t)b * 1024 + lane * 32);
        float4* tr = (float4*)(tP + lane * P_ST);
#pragma unroll
        for (int j4 = 0; j4 < 8; j4++) tr[j4] = Pr[j4];
    }
    __syncwarp();
    tP[lane * P_ST + lane] += eQs[lane];
    __syncwarp();

    // ===== M row `lane` = H[lane][:] @ P  (f64 accum). Doubles as RHS. =====
    double bb[32];
#pragma unroll
    for (int j = 0; j < 32; j++) bb[j] = 0.0;
#pragma unroll
    for (int k = 0; k < 32; k++) {
        double hk = (double)hrow[k];
        const float4* pr = (const float4*)(tP + k * P_ST);
#pragma unroll
        for (int j4 = 0; j4 < 8; j4++) {
            float4 p4 = pr[j4];
            bb[4 * j4 + 0] = fma(hk, (double)p4.x, bb[4 * j4 + 0]);
            bb[4 * j4 + 1] = fma(hk, (double)p4.y, bb[4 * j4 + 1]);
            bb[4 * j4 + 2] = fma(hk, (double)p4.z, bb[4 * j4 + 2]);
            bb[4 * j4 + 3] = fma(hk, (double)p4.w, bb[4 * j4 + 3]);
        }
    }

    // ===== S row `lane` = M[lane][:] @ H^T + diag(eR)  (f64) =====
    double s[32];
#pragma unroll
    for (int k = 0; k < 32; k++) {
        const float4* hr = (const float4*)(Hs + k * H_ST);
        double acc = 0.0;
#pragma unroll
        for (int j4 = 0; j4 < 8; j4++) {
            float4 h4 = hr[j4];
            acc = fma(bb[4 * j4 + 0], (double)h4.x, acc);
            acc = fma(bb[4 * j4 + 1], (double)h4.y, acc);
            acc = fma(bb[4 * j4 + 2], (double)h4.z, acc);
            acc = fma(bb[4 * j4 + 3], (double)h4.w, acc);
        }
        if (k == lane) acc += (double)eRs[lane];
        s[k] = acc;
    }

    // ===== f64 LU, partial pivoting (virtual swaps), RHS carried =====
    int    myk   = 32;
    int    mypiv = 0;
    double myinv = 0.0;
    bool   done  = false;

#pragma unroll
    for (int k = 0; k < 32; k++) {
        float cand = done ? -1.0f : fabsf((float)s[k]);
        int   idx  = lane;
#pragma unroll
        for (int off = 16; off > 0; off >>= 1) {
            float oc = __shfl_xor_sync(FULL, cand, off);
            int   oi = __shfl_xor_sync(FULL, idx,  off);
            if (oc > cand || (oc == cand && oi < idx)) { cand = oc; idx = oi; }
        }
        if (lane == k) mypiv = idx;
        double dk   = __shfl_sync(FULL, s[k], idx);
        double invd = 1.0 / dk;
        if (lane == idx) { myk = k; myinv = invd; done = true; }
        double mult = done ? 0.0 : s[k] * invd;
#pragma unroll
        for (int j = k + 1; j < 32; j++) {
            double uj = __shfl_sync(FULL, s[j], idx);
            s[j] = fma(-mult, uj, s[j]);
        }
#pragma unroll
        for (int j = 0; j < 32; j++) {
            double wj = __shfl_sync(FULL, bb[j], idx);
            bb[j] = fma(-mult, wj, bb[j]);
        }
    }

    // ===== f64 backward substitution (reverse pivot order) =====
#pragma unroll
    for (int k = 31; k >= 0; k--) {
        int pk = __shfl_sync(FULL, mypiv, k);
        if (myk == k) {
#pragma unroll
            for (int j = 0; j < 32; j++) bb[j] *= myinv;
        }
#pragma unroll
        for (int j = 0; j < 32; j++) {
            double xk = __shfl_sync(FULL, bb[j], pk);
            if (myk < k) bb[j] = fma(-s[k], xk, bb[j]);
        }
    }

    // X row `myk` -> shared (single f32 rounding, benign)
    {
        float* xr = u.xt[w] + myk * X_ST;
#pragma unroll
        for (int j = 0; j < 32; j++) xr[j] = (float)bb[j];
    }
    __syncwarp();

    // ===== downstream (f32): K = X^T =====
    float xcol[32];
#pragma unroll
    for (int i = 0; i < 32; i++) xcol[i] = u.xt[w][i * X_ST + lane];

    float xo = xp;
#pragma unroll
    for (int j = 0; j < 32; j++) xo = fmaf(xcol[j], ybuf[w][j], xo);
    out_x[(size_t)b * 32 + lane] = xo;

    // A row t = I - K H
    float g2[32];
#pragma unroll
    for (int j = 0; j < 32; j++) g2[j] = 0.f;
#pragma unroll
    for (int i = 0; i < 32; i++) {
        float kv = xcol[i];
        const float4* hr = (const float4*)(Hs + i * H_ST);
#pragma unroll
        for (int j4 = 0; j4 < 8; j4++) {
            float4 h4 = hr[j4];
            g2[4 * j4 + 0] = fmaf(kv, h4.x, g2[4 * j4 + 0]);
            g2[4 * j4 + 1] = fmaf(kv, h4.y, g2[4 * j4 + 1]);
            g2[4 * j4 + 2] = fmaf(kv, h4.z, g2[4 * j4 + 2]);
            g2[4 * j4 + 3] = fmaf(kv, h4.w, g2[4 * j4 + 3]);
        }
    }
#pragma unroll
    for (int j = 0; j < 32; j++)
        g2[j] = ((j == lane) ? 1.0f : 0.0f) - g2[j];

    // P_upd row t = A[t][:] @ P_pred
    float pu[32];
#pragma unroll
    for (int j = 0; j < 32; j++) pu[j] = 0.f;
#pragma unroll
    for (int k = 0; k < 32; k++) {
        float ak = g2[k];
        const float4* pr = (const float4*)(tP + k * P_ST);
#pragma unroll
        for (int j4 = 0; j4 < 8; j4++) {
            float4 p4 = pr[j4];
            pu[4 * j4 + 0] = fmaf(ak, p4.x, pu[4 * j4 + 0]);
            pu[4 * j4 + 1] = fmaf(ak, p4.y, pu[4 * j4 + 1]);
            pu[4 * j4 + 2] = fmaf(ak, p4.z, pu[4 * j4 + 2]);
            pu[4 * j4 + 3] = fmaf(ak, p4.w, pu[4 * j4 + 3]);
        }
    }
    float4* Po = (float4*)(out_P + (size_t)b * 1024 + lane * 32);
#pragma unroll
    for (int j4 = 0; j4 < 8; j4++)
        Po[j4] = make_float4(pu[4 * j4], pu[4 * j4 + 1], pu[4 * j4 + 2], pu[4 * j4 + 3]);
}

extern "C" void kernel_launch(void* const* d_in, const int* in_sizes, int n_in,
                              void* d_out, int out_size) {
    const float* x_post = (const float*)d_in[0];
    const float* P_post = (const float*)d_in[1];
    const float* ctx    = (const float*)d_in[2];
    const float* meas   = (const float*)d_in[3];
    const float* W1     = (const float*)d_in[4];
    const float* b1     = (const float*)d_in[5];
    const float* W2     = (const float*)d_in[6];
    const float* b2     = (const float*)d_in[7];
    const float* Hm     = (const float*)d_in[8];
    const float* logQ   = (const float*)d_in[9];
    const float* logR   = (const float*)d_in[10];

    float* out_x = (float*)d_out;
    float* out_P = out_x + (size_t)BATCH * 32;

    kalman_kernel<<<BATCH / WPB, TPB>>>(x_post, P_post, ctx, meas,
                                        W1, b1, W2, b2, Hm, logQ, logR,
                                        out_x, out_P);
}

// round 13
// speedup vs baseline: 8.5186x; 8.5186x over previous
#include <cuda_runtime.h>
#include <math.h>

#define BATCH 65536
#define WPB   4
#define TPB   128
#define H_ST  36
#define P_ST  36
#define V_ST  36
#define W1_ST 49
#define W2_ST 65
#define FULL  0xffffffffu

// ---------- double-float (compensated f32) primitives ----------
__device__ __forceinline__ void acc2(float a, float b, float& sh, float& sl) {
    float p = a * b;
    float e = fmaf(a, b, -p);
    float t = sh + p;
    float z = t - sh;
    sl += ((sh - (t - z)) + (p - z)) + e;
    sh = t;
}
__device__ __forceinline__ void acc2df(float ah, float al, float b, float& sh, float& sl) {
    float p = ah * b;
    float e = fmaf(ah, b, -p);
    e = fmaf(al, b, e);
    float t = sh + p;
    float z = t - sh;
    sl += ((sh - (t - z)) + (p - z)) + e;
    sh = t;
}
__device__ __forceinline__ void sub2(float ah, float al, float bh, float bl,
                                     float& rh, float& rl) {
    float p = ah * bh;
    float e = fmaf(ah, bh, -p);
    e = fmaf(ah, bl, e);
    e = fmaf(al, bh, e);
    float t = rh - p;
    float z = t - rh;
    rl += ((rh - (t - z)) - (p + z)) - e;
    rh = t;
}
__device__ __forceinline__ void dmul(float ah, float al, float bh, float bl,
                                     float& ph, float& pl) {
    ph = ah * bh;
    pl = fmaf(ah, bh, -ph);
    pl = fmaf(ah, bl, pl);
    pl = fmaf(al, bh, pl);
}
__device__ __forceinline__ void drecip(float dh, float dl, float& qh, float& ql) {
    float q = 1.0f / dh;
    float e = fmaf(-q, dh, 1.0f);
    e = fmaf(-q, dl, e);
    float q1 = q * e;
    float t = q + q1;
    ql = (q - t) + q1;
    qh = t;
}

__global__ void __launch_bounds__(TPB, 3) kalman_kernel(
    const float* __restrict__ x_post, const float* __restrict__ P_post,
    const float* __restrict__ ctx,    const float* __restrict__ meas,
    const float* __restrict__ W1,     const float* __restrict__ b1,
    const float* __restrict__ W2,     const float* __restrict__ b2,
    const float* __restrict__ Hm,     const float* __restrict__ logQ,
    const float* __restrict__ logR,
    float* __restrict__ out_x, float* __restrict__ out_P)
{
    __shared__ __align__(16) float Hs[32 * H_ST];
    __shared__ __align__(16) union SU {
        struct { float W1s[64 * W1_ST]; float W2s[32 * W2_ST]; } m;  // MLP phase
        float vt[WPB][32 * V_ST];   // V rows (unscaled); col 32 = z * d^{-1}
    } u;
    __shared__ __align__(16) float Pt[WPB][32 * P_ST];   // P_pred rows (f32)
    __shared__ float b1s[64], b2s[32], eQs[32], eRs[32];
    __shared__ float mlpbuf[WPB][64];
    __shared__ float dinvs[WPB][32];

    const int tid = threadIdx.x;
    for (int i = tid; i < 64 * 48; i += TPB) u.m.W1s[(i / 48) * W1_ST + (i % 48)] = W1[i];
    for (int i = tid; i < 32 * 64; i += TPB) u.m.W2s[(i >> 6) * W2_ST + (i & 63)] = W2[i];
    for (int i = tid; i < 32 * 32; i += TPB) Hs[(i >> 5) * H_ST + (i & 31)] = Hm[i];
    if (tid < 64) b1s[tid] = b1[tid];
    if (tid < 32) {
        b2s[tid] = b2[tid];
        eQs[tid] = expf(logQ[tid]);
        eRs[tid] = expf(logR[tid]) + 1e-6f;
    }
    __syncthreads();

    const int w    = tid >> 5;
    const int lane = tid & 31;
    const int b    = blockIdx.x * WPB + w;
    float* tP = Pt[w];
    float* tV = u.vt[w];

    float hrow[32];
#pragma unroll
    for (int j = 0; j < 32; j++) hrow[j] = Hs[lane * H_ST + j];

    // ===================== MLP (f32, noise-benign) =====================
    mlpbuf[w][lane] = x_post[(size_t)b * 32 + lane];
    if (lane < 16) mlpbuf[w][32 + lane] = ctx[(size_t)b * 16 + lane];
    __syncwarp();

    float a0 = b1s[lane], a1 = b1s[lane + 32];
#pragma unroll
    for (int j = 0; j < 48; j++) {
        float vj = mlpbuf[w][j];
        a0 = fmaf(u.m.W1s[lane * W1_ST + j], vj, a0);
        a1 = fmaf(u.m.W1s[(lane + 32) * W1_ST + j], vj, a1);
    }
    float h0 = tanhf(a0), h1 = tanhf(a1);
    __syncwarp();
    mlpbuf[w][lane]      = h0;
    mlpbuf[w][lane + 32] = h1;
    __syncwarp();

    float xp = b2s[lane];
#pragma unroll
    for (int k = 0; k < 64; k++) xp = fmaf(u.m.W2s[lane * W2_ST + k], mlpbuf[w][k], xp);
    __syncwarp();
    mlpbuf[w][lane] = xp;
    __syncwarp();

    float yv = meas[(size_t)b * 32 + lane];
#pragma unroll
    for (int j = 0; j < 32; j++) yv = fmaf(-mlpbuf[w][j], hrow[j], yv);

    // All warps done with W1/W2 before the V overlay is written.
    __syncthreads();

    // ===== P_pred rows into shared =====
    {
        const float4* Pr = (const float4*)(P_post + (size_t)b * 1024 + lane * 32);
        float4* tr = (float4*)(tP + lane * P_ST);
#pragma unroll
        for (int j4 = 0; j4 < 8; j4++) tr[j4] = Pr[j4];
    }
    __syncwarp();
    tP[lane * P_ST + lane] += eQs[lane];
    __syncwarp();

    // ===== M row `lane` = H[lane][:] @ P  (df Dot2) =====
    float mh[32], ml[32];
#pragma unroll
    for (int j = 0; j < 32; j++) { mh[j] = 0.f; ml[j] = 0.f; }
#pragma unroll
    for (int k = 0; k < 32; k++) {
        float hk = hrow[k];
        const float4* pr = (const float4*)(tP + k * P_ST);
#pragma unroll
        for (int j4 = 0; j4 < 8; j4++) {
            float4 p4 = pr[j4];
            acc2(hk, p4.x, mh[4 * j4 + 0], ml[4 * j4 + 0]);
            acc2(hk, p4.y, mh[4 * j4 + 1], ml[4 * j4 + 1]);
            acc2(hk, p4.z, mh[4 * j4 + 2], ml[4 * j4 + 2]);
            acc2(hk, p4.w, mh[4 * j4 + 3], ml[4 * j4 + 3]);
        }
    }

    // ===== S row `lane` = M_df @ H^T + diag(eR)  (df) =====
    float sh[32], sl[32];
#pragma unroll
    for (int k = 0; k < 32; k++) {
        const float4* hr = (const float4*)(Hs + k * H_ST);
        float ach = 0.f, acl = 0.f;
#pragma unroll
        for (int j4 = 0; j4 < 8; j4++) {
            float4 h4 = hr[j4];
            acc2df(mh[4 * j4 + 0], ml[4 * j4 + 0], h4.x, ach, acl);
            acc2df(mh[4 * j4 + 1], ml[4 * j4 + 1], h4.y, ach, acl);
            acc2df(mh[4 * j4 + 2], ml[4 * j4 + 2], h4.z, ach, acl);
            acc2df(mh[4 * j4 + 3], ml[4 * j4 + 3], h4.w, ach, acl);
        }
        if (k == lane) {   // += eR, exact TwoSum
            float eR = eRs[lane];
            float t = ach + eR;
            float z = t - ach;
            acl += (ach - (t - z)) + (eR - z);
            ach = t;
        }
        sh[k] = ach; sl[k] = acl;
    }

    // RHS rows (f32): [M | y]
    float v[33];
#pragma unroll
    for (int j = 0; j < 32; j++) v[j] = mh[j] + ml[j];
    v[32] = yv;

    // ===== unpivoted signed-D LDL (df on S), f32 RHS forward-subst =====
    // Lane = row. At step k: d_k = lane k's s[k] (may be negative, never
    // sqrt'ed); multiplier L[t][k] = s[k]/d_k from lane t's own register
    // (symmetry). Lane k freezes at step k and archives its d^{-1} (df).
    float myih = 0.f, myil = 0.f;
#pragma unroll
    for (int k = 0; k < 32; k++) {
        float dkh = __shfl_sync(FULL, sh[k], k);
        float dkl = __shfl_sync(FULL, sl[k], k);
        float ih, il; drecip(dkh, dkl, ih, il);
        if (lane == k) { myih = ih; myil = il; }
        float multh, multl;
        dmul(sh[k], sl[k], ih, il, multh, multl);
        if (lane <= k) { multh = 0.f; multl = 0.f; }
        float lf = multh + multl;
#pragma unroll
        for (int j = k + 1; j < 32; j++) {
            float uh = __shfl_sync(FULL, sh[j], k);
            float ul = __shfl_sync(FULL, sl[j], k);
            sub2(multh, multl, uh, ul, sh[j], sl[j]);
        }
#pragma unroll
        for (int j = 0; j < 33; j++) {
            float vk = __shfl_sync(FULL, v[j], k);
            v[j] = fmaf(-lf, vk, v[j]);
        }
    }

    // ===== stage V rows (unscaled) + z*d^{-1}; archive d^{-1} =====
    {
        float dinv = myih + myil;
        float* vr = tV + lane * V_ST;
#pragma unroll
        for (int j = 0; j < 32; j++) vr[j] = v[j];
        vr[32] = v[32] * dinv;
        dinvs[w][lane] = dinv;
    }
    __syncwarp();

    // ===== fused x_upd & P_upd =====
    // x_upd[t] = xp + Σ_k V[k][t] * (z_k d_k^{-1})
    // P_upd[t][:] = P[t][:] - Σ_k (V[k][t] d_k^{-1}) * V[k][:]
    float xo = xp;
    float pu[32];
    {
        const float4* pr = (const float4*)(tP + lane * P_ST);
#pragma unroll
        for (int j4 = 0; j4 < 8; j4++) {
            float4 p4 = pr[j4];
            pu[4 * j4 + 0] = p4.x; pu[4 * j4 + 1] = p4.y;
            pu[4 * j4 + 2] = p4.z; pu[4 * j4 + 3] = p4.w;
        }
    }
#pragma unroll
    for (int k = 0; k < 32; k++) {
        const float* vr = tV + k * V_ST;
        float vt = vr[lane];
        xo = fmaf(vt, vr[32], xo);
        float a = vt * dinvs[w][k];
        const float4* vr4 = (const float4*)vr;
#pragma unroll
        for (int j4 = 0; j4 < 8; j4++) {
            float4 v4 = vr4[j4];
            pu[4 * j4 + 0] = fmaf(-a, v4.x, pu[4 * j4 + 0]);
            pu[4 * j4 + 1] = fmaf(-a, v4.y, pu[4 * j4 + 1]);
            pu[4 * j4 + 2] = fmaf(-a, v4.z, pu[4 * j4 + 2]);
            pu[4 * j4 + 3] = fmaf(-a, v4.w, pu[4 * j4 + 3]);
        }
    }
    out_x[(size_t)b * 32 + lane] = xo;
    float4* Po = (float4*)(out_P + (size_t)b * 1024 + lane * 32);
#pragma unroll
    for (int j4 = 0; j4 < 8; j4++)
        Po[j4] = make_float4(pu[4 * j4], pu[4 * j4 + 1], pu[4 * j4 + 2], pu[4 * j4 + 3]);
}

extern "C" void kernel_launch(void* const* d_in, const int* in_sizes, int n_in,
                              void* d_out, int out_size) {
    const float* x_post = (const float*)d_in[0];
    const float* P_post = (const float*)d_in[1];
    const float* ctx    = (const float*)d_in[2];
    const float* meas   = (const float*)d_in[3];
    const float* W1     = (const float*)d_in[4];
    const float* b1     = (const float*)d_in[5];
    const float* W2     = (const float*)d_in[6];
    const float* b2     = (const float*)d_in[7];
    const float* Hm     = (const float*)d_in[8];
    const float* logQ   = (const float*)d_in[9];
    const float* logR   = (const float*)d_in[10];

    float* out_x = (float*)d_out;
    float* out_P = out_x + (size_t)BATCH * 32;

    kalman_kernel<<<BATCH / WPB, TPB>>>(x_post, P_post, ctx, meas,
                                        W1, b1, W2, b2, Hm, logQ, logR,
                                        out_x, out_P);
}

// round 14
// speedup vs baseline: 16.6575x; 1.9554x over previous
#include <cuda_runtime.h>
#include <math.h>

#define BATCH 65536
#define WPB   4
#define TPB   128
#define H_ST  36
#define P_ST  36
#define V_ST  36
#define W1_ST 49
#define W2_ST 65
#define FULL  0xffffffffu

typedef unsigned long long u64;

// ---------- packed f32x2 primitives (sm_100+ PTX) ----------
__device__ __forceinline__ u64 pmul(u64 a, u64 b) {
    u64 r; asm("mul.rn.f32x2 %0,%1,%2;" : "=l"(r) : "l"(a), "l"(b)); return r;
}
__device__ __forceinline__ u64 padd(u64 a, u64 b) {
    u64 r; asm("add.rn.f32x2 %0,%1,%2;" : "=l"(r) : "l"(a), "l"(b)); return r;
}
__device__ __forceinline__ u64 psub(u64 a, u64 b) {
    u64 r; asm("sub.rn.f32x2 %0,%1,%2;" : "=l"(r) : "l"(a), "l"(b)); return r;
}
__device__ __forceinline__ u64 pfma(u64 a, u64 b, u64 c) {
    u64 r; asm("fma.rn.f32x2 %0,%1,%2,%3;" : "=l"(r) : "l"(a), "l"(b), "l"(c)); return r;
}
__device__ __forceinline__ u64 pneg(u64 a) { return a ^ 0x8000000080000000ULL; }
__device__ __forceinline__ u64 pk2(float lo, float hi) {
    u64 r; asm("mov.b64 %0, {%1,%2};" : "=l"(r) : "f"(lo), "f"(hi)); return r;
}
__device__ __forceinline__ void upk(u64 v, float& lo, float& hi) {
    asm("mov.b64 {%0,%1}, %2;" : "=f"(lo), "=f"(hi) : "l"(v));
}

// packed Dot2: (sh,sl) += a*b
__device__ __forceinline__ void acc2p(u64 a, u64 b, u64& sh, u64& sl) {
    u64 p = pmul(a, b);
    u64 e = pfma(a, b, pneg(p));
    u64 t = padd(sh, p);
    u64 z = psub(t, sh);
    sl = padd(sl, padd(padd(psub(sh, psub(t, z)), psub(p, z)), e));
    sh = t;
}
// packed: (sh,sl) += (ah,al)*b
__device__ __forceinline__ void acc2dfp(u64 ah, u64 al, u64 b, u64& sh, u64& sl) {
    u64 p = pmul(ah, b);
    u64 e = pfma(ah, b, pneg(p));
    e = pfma(al, b, e);
    u64 t = padd(sh, p);
    u64 z = psub(t, sh);
    sl = padd(sl, padd(padd(psub(sh, psub(t, z)), psub(p, z)), e));
    sh = t;
}
// packed: (rh,rl) -= (ah,al)*(bh,bl)
__device__ __forceinline__ void sub2p(u64 ah, u64 al, u64 bh, u64 bl,
                                      u64& rh, u64& rl) {
    u64 p = pmul(ah, bh);
    u64 e = pfma(ah, bh, pneg(p));
    e = pfma(ah, bl, e);
    e = pfma(al, bh, e);
    u64 t = psub(rh, p);
    u64 z = psub(t, rh);
    rl = padd(rl, psub(psub(psub(rh, psub(t, z)), padd(p, z)), e));
    rh = t;
}
// scalar df helpers (pivot path only)
__device__ __forceinline__ void dmul(float ah, float al, float bh, float bl,
                                     float& ph, float& pl) {
    ph = ah * bh;
    pl = fmaf(ah, bh, -ph);
    pl = fmaf(ah, bl, pl);
    pl = fmaf(al, bh, pl);
}
__device__ __forceinline__ void drecip(float dh, float dl, float& qh, float& ql) {
    float q = 1.0f / dh;
    float e = fmaf(-q, dh, 1.0f);
    e = fmaf(-q, dl, e);
    float q1 = q * e;
    float t = q + q1;
    ql = (q - t) + q1;
    qh = t;
}

__global__ void __launch_bounds__(TPB, 3) kalman_kernel(
    const float* __restrict__ x_post, const float* __restrict__ P_post,
    const float* __restrict__ ctx,    const float* __restrict__ meas,
    const float* __restrict__ W1,     const float* __restrict__ b1,
    const float* __restrict__ W2,     const float* __restrict__ b2,
    const float* __restrict__ Hm,     const float* __restrict__ logQ,
    const float* __restrict__ logR,
    float* __restrict__ out_x, float* __restrict__ out_P)
{
    __shared__ __align__(16) float Hs[32 * H_ST];
    __shared__ __align__(16) union SU {
        struct { float W1s[64 * W1_ST]; float W2s[32 * W2_ST]; } m;  // MLP phase
        float vt[WPB][32 * V_ST];   // V rows (unscaled); col 32 = z * d^{-1}
    } u;
    __shared__ __align__(16) float Pt[WPB][32 * P_ST];   // P_pred rows (f32)
    __shared__ float b1s[64], b2s[32], eQs[32], eRs[32];
    __shared__ float mlpbuf[WPB][64];
    __shared__ float dinvs[WPB][32];

    const int tid = threadIdx.x;
    for (int i = tid; i < 64 * 48; i += TPB) u.m.W1s[(i / 48) * W1_ST + (i % 48)] = W1[i];
    for (int i = tid; i < 32 * 64; i += TPB) u.m.W2s[(i >> 6) * W2_ST + (i & 63)] = W2[i];
    for (int i = tid; i < 32 * 32; i += TPB) Hs[(i >> 5) * H_ST + (i & 31)] = Hm[i];
    if (tid < 64) b1s[tid] = b1[tid];
    if (tid < 32) {
        b2s[tid] = b2[tid];
        eQs[tid] = expf(logQ[tid]);
        eRs[tid] = expf(logR[tid]) + 1e-6f;
    }
    __syncthreads();

    const int w    = tid >> 5;
    const int lane = tid & 31;
    const int b    = blockIdx.x * WPB + w;
    float* tP = Pt[w];
    float* tV = u.vt[w];

    // ===================== MLP (f32, noise-benign) =====================
    mlpbuf[w][lane] = x_post[(size_t)b * 32 + lane];
    if (lane < 16) mlpbuf[w][32 + lane] = ctx[(size_t)b * 16 + lane];
    __syncwarp();

    float a0 = b1s[lane], a1 = b1s[lane + 32];
#pragma unroll
    for (int j = 0; j < 48; j++) {
        float vj = mlpbuf[w][j];
        a0 = fmaf(u.m.W1s[lane * W1_ST + j], vj, a0);
        a1 = fmaf(u.m.W1s[(lane + 32) * W1_ST + j], vj, a1);
    }
    float h0 = tanhf(a0), h1 = tanhf(a1);
    __syncwarp();
    mlpbuf[w][lane]      = h0;
    mlpbuf[w][lane + 32] = h1;
    __syncwarp();

    float xp = b2s[lane];
#pragma unroll
    for (int k = 0; k < 64; k++) xp = fmaf(u.m.W2s[lane * W2_ST + k], mlpbuf[w][k], xp);
    __syncwarp();
    mlpbuf[w][lane] = xp;
    __syncwarp();

    float yv = meas[(size_t)b * 32 + lane];
#pragma unroll
    for (int j = 0; j < 32; j++) yv = fmaf(-mlpbuf[w][j], Hs[lane * H_ST + j], yv);

    // All warps done with W1/W2 before the V overlay is written.
    __syncthreads();

    // ===== P_pred rows into shared =====
    {
        const float4* Pr = (const float4*)(P_post + (size_t)b * 1024 + lane * 32);
        float4* tr = (float4*)(tP + lane * P_ST);
#pragma unroll
        for (int j4 = 0; j4 < 8; j4++) tr[j4] = Pr[j4];
    }
    __syncwarp();
    tP[lane * P_ST + lane] += eQs[lane];
    __syncwarp();

    // ===== M row `lane` = H[lane][:] @ P  (packed df Dot2) =====
    u64 pmh[16], pml[16];
#pragma unroll
    for (int p = 0; p < 16; p++) { pmh[p] = 0ULL; pml[p] = 0ULL; }
#pragma unroll
    for (int k = 0; k < 32; k++) {
        float hk = Hs[lane * H_ST + k];
        u64 hk2 = pk2(hk, hk);
        const ulonglong2* pr = (const ulonglong2*)(tP + k * P_ST);
#pragma unroll
        for (int q = 0; q < 8; q++) {
            ulonglong2 two = pr[q];
            acc2p(hk2, two.x, pmh[2 * q + 0], pml[2 * q + 0]);
            acc2p(hk2, two.y, pmh[2 * q + 1], pml[2 * q + 1]);
        }
    }

    // ===== S row `lane` = M_df @ H^T + diag(eR)  (packed df, scalar merge) =====
    u64 psh[16], psl[16];
    {
        float t0h = 0.f, t0l = 0.f;
#pragma unroll
        for (int k = 0; k < 32; k++) {
            const ulonglong2* hr = (const ulonglong2*)(Hs + k * H_ST);
            u64 ach = 0ULL, acl = 0ULL;
#pragma unroll
            for (int q = 0; q < 8; q++) {
                ulonglong2 two = hr[q];
                acc2dfp(pmh[2 * q + 0], pml[2 * q + 0], two.x, ach, acl);
                acc2dfp(pmh[2 * q + 1], pml[2 * q + 1], two.y, ach, acl);
            }
            // horizontal combine of the two packed halves (TwoSum)
            float a0, a1, c0, c1;
            upk(ach, a0, a1);
            upk(acl, c0, c1);
            float th = a0 + a1;
            float zz = th - a0;
            float tl = ((a0 - (th - zz)) + (a1 - zz)) + (c0 + c1);
            if (k == lane) {   // += eR, exact TwoSum
                float eR = eRs[lane];
                float t2 = th + eR;
                float z2 = t2 - th;
                tl += (th - (t2 - z2)) + (eR - z2);
                th = t2;
            }
            if ((k & 1) == 0) { t0h = th; t0l = tl; }
            else { psh[k >> 1] = pk2(t0h, th); psl[k >> 1] = pk2(t0l, tl); }
        }
    }

    // RHS packs (f32): pv = f32(M); y carried scalar
    u64 pv[16];
#pragma unroll
    for (int p = 0; p < 16; p++) pv[p] = padd(pmh[p], pml[p]);

    // ===== unpivoted signed-D LDL (packed df S), f32 RHS forward-subst =====
    float myih = 0.f, myil = 0.f;
#pragma unroll
    for (int k = 0; k < 32; k++) {
        const int kp = k >> 1;
        // pivot d_k from lane k (broadcast packed, static half select)
        u64 bsh = __shfl_sync(FULL, psh[kp], k);
        u64 bsl = __shfl_sync(FULL, psl[kp], k);
        float dkh, dkl, t0, t1;
        if (k & 1) { upk(bsh, t0, dkh); upk(bsl, t1, dkl); }
        else       { upk(bsh, dkh, t0); upk(bsl, dkl, t1); }
        float ih, il; drecip(dkh, dkl, ih, il);
        if (lane == k) { myih = ih; myil = il; }
        // own s[k] (static half select)
        float skh, skl;
        if (k & 1) { upk(psh[kp], t0, skh); upk(psl[kp], t1, skl); }
        else       { upk(psh[kp], skh, t0); upk(psl[kp], skl, t1); }
        float mh_, ml_;
        dmul(skh, skl, ih, il, mh_, ml_);
        if (lane <= k) { mh_ = 0.f; ml_ = 0.f; }
        u64 pm2 = pk2(mh_, mh_), pl2 = pk2(ml_, ml_);
        float lf = mh_ + ml_;
        // S elimination on packs >= (k+1)>>1. For even k the first pack also
        // contains entry k, which is spuriously updated — it is never read
        // after this step (pivot, multiplier, archive all read before).
#pragma unroll
        for (int p = (k + 1) >> 1; p < 16; p++) {
            u64 buh = __shfl_sync(FULL, psh[p], k);
            u64 bul = __shfl_sync(FULL, psl[p], k);
            sub2p(pm2, pl2, buh, bul, psh[p], psl[p]);
        }
        // RHS forward substitution (f32, packed)
        u64 plfn = pk2(-lf, -lf);
#pragma unroll
        for (int p = 0; p < 16; p++) {
            u64 bv = __shfl_sync(FULL, pv[p], k);
            pv[p] = pfma(plfn, bv, pv[p]);
        }
        float by = __shfl_sync(FULL, yv, k);
        yv = fmaf(-lf, by, yv);
    }

    // ===== stage V rows (unscaled) + z*d^{-1}; archive d^{-1} =====
    {
        float dinv = myih + myil;
        u64* vr = (u64*)(tV + lane * V_ST);
#pragma unroll
        for (int p = 0; p < 16; p++) vr[p] = pv[p];
        tV[lane * V_ST + 32] = yv * dinv;
        dinvs[w][lane] = dinv;
    }
    __syncwarp();

    // ===== fused x_upd & P_upd (packed rank-32 Schur update) =====
    float xo = xp;
    u64 pu[16];
    {
        const ulonglong2* pr = (const ulonglong2*)(tP + lane * P_ST);
#pragma unroll
        for (int q = 0; q < 8; q++) {
            ulonglong2 two = pr[q];
            pu[2 * q + 0] = two.x;
            pu[2 * q + 1] = two.y;
        }
    }
#pragma unroll
    for (int k = 0; k < 32; k++) {
        const float* vrk = tV + k * V_ST;
        float vt = vrk[lane];
        xo = fmaf(vt, vrk[32], xo);
        float a = vt * dinvs[w][k];
        u64 pa = pk2(-a, -a);
        const ulonglong2* vr2 = (const ulonglong2*)vrk;
#pragma unroll
        for (int q = 0; q < 8; q++) {
            ulonglong2 two = vr2[q];
            pu[2 * q + 0] = pfma(pa, two.x, pu[2 * q + 0]);
            pu[2 * q + 1] = pfma(pa, two.y, pu[2 * q + 1]);
        }
    }
    out_x[(size_t)b * 32 + lane] = xo;
    ulonglong2* Po = (ulonglong2*)(out_P + (size_t)b * 1024 + lane * 32);
#pragma unroll
    for (int q = 0; q < 8; q++)
        Po[q] = make_ulonglong2(pu[2 * q], pu[2 * q + 1]);
}

extern "C" void kernel_launch(void* const* d_in, const int* in_sizes, int n_in,
                              void* d_out, int out_size) {
    const float* x_post = (const float*)d_in[0];
    const float* P_post = (const float*)d_in[1];
    const float* ctx    = (const float*)d_in[2];
    const float* meas   = (const float*)d_in[3];
    const float* W1     = (const float*)d_in[4];
    const float* b1     = (const float*)d_in[5];
    const float* W2     = (const float*)d_in[6];
    const float* b2     = (const float*)d_in[7];
    const float* Hm     = (const float*)d_in[8];
    const float* logQ   = (const float*)d_in[9];
    const float* logR   = (const float*)d_in[10];

    float* out_x = (float*)d_out;
    float* out_P = out_x + (size_t)BATCH * 32;

    kalman_kernel<<<BATCH / WPB, TPB>>>(x_post, P_post, ctx, meas,
                                        W1, b1, W2, b2, Hm, logQ, logR,
                                        out_x, out_P);
}

// round 15
// speedup vs baseline: 17.0579x; 1.0240x over previous
#include <cuda_runtime.h>
#include <math.h>

#define BATCH 65536
#define WPB   4
#define TPB   128
#define H_ST  36
#define P_ST  36
#define V_ST  36
#define W1_ST 49
#define W2_ST 65
#define FULL  0xffffffffu

typedef unsigned long long u64;

// ---------- packed f32x2 primitives (sm_100+ PTX) ----------
__device__ __forceinline__ u64 pmul(u64 a, u64 b) {
    u64 r; asm("mul.rn.f32x2 %0,%1,%2;" : "=l"(r) : "l"(a), "l"(b)); return r;
}
__device__ __forceinline__ u64 padd(u64 a, u64 b) {
    u64 r; asm("add.rn.f32x2 %0,%1,%2;" : "=l"(r) : "l"(a), "l"(b)); return r;
}
__device__ __forceinline__ u64 psub(u64 a, u64 b) {
    u64 r; asm("sub.rn.f32x2 %0,%1,%2;" : "=l"(r) : "l"(a), "l"(b)); return r;
}
__device__ __forceinline__ u64 pfma(u64 a, u64 b, u64 c) {
    u64 r; asm("fma.rn.f32x2 %0,%1,%2,%3;" : "=l"(r) : "l"(a), "l"(b), "l"(c)); return r;
}
__device__ __forceinline__ u64 pneg(u64 a) { return a ^ 0x8000000080000000ULL; }
__device__ __forceinline__ u64 pk2(float lo, float hi) {
    u64 r; asm("mov.b64 %0, {%1,%2};" : "=l"(r) : "f"(lo), "f"(hi)); return r;
}
__device__ __forceinline__ void upk(u64 v, float& lo, float& hi) {
    asm("mov.b64 {%0,%1}, %2;" : "=f"(lo), "=f"(hi) : "l"(v));
}

// packed Dot2: (sh,sl) += a*b
__device__ __forceinline__ void acc2p(u64 a, u64 b, u64& sh, u64& sl) {
    u64 p = pmul(a, b);
    u64 e = pfma(a, b, pneg(p));
    u64 t = padd(sh, p);
    u64 z = psub(t, sh);
    sl = padd(sl, padd(padd(psub(sh, psub(t, z)), psub(p, z)), e));
    sh = t;
}
// packed: (sh,sl) += (ah,al)*b
__device__ __forceinline__ void acc2dfp(u64 ah, u64 al, u64 b, u64& sh, u64& sl) {
    u64 p = pmul(ah, b);
    u64 e = pfma(ah, b, pneg(p));
    e = pfma(al, b, e);
    u64 t = padd(sh, p);
    u64 z = psub(t, sh);
    sl = padd(sl, padd(padd(psub(sh, psub(t, z)), psub(p, z)), e));
    sh = t;
}
// packed: (rh,rl) -= (ah,al)*(bh,bl)
__device__ __forceinline__ void sub2p(u64 ah, u64 al, u64 bh, u64 bl,
                                      u64& rh, u64& rl) {
    u64 p = pmul(ah, bh);
    u64 e = pfma(ah, bh, pneg(p));
    e = pfma(ah, bl, e);
    e = pfma(al, bh, e);
    u64 t = psub(rh, p);
    u64 z = psub(t, rh);
    rl = padd(rl, psub(psub(psub(rh, psub(t, z)), padd(p, z)), e));
    rh = t;
}
// scalar df helpers (pivot path only)
__device__ __forceinline__ void dmul(float ah, float al, float bh, float bl,
                                     float& ph, float& pl) {
    ph = ah * bh;
    pl = fmaf(ah, bh, -ph);
    pl = fmaf(ah, bl, pl);
    pl = fmaf(al, bh, pl);
}
__device__ __forceinline__ void drecip(float dh, float dl, float& qh, float& ql) {
    float q = 1.0f / dh;
    float e = fmaf(-q, dh, 1.0f);
    e = fmaf(-q, dl, e);
    float q1 = q * e;
    float t = q + q1;
    ql = (q - t) + q1;
    qh = t;
}

__global__ void __launch_bounds__(TPB, 4) kalman_kernel(
    const float* __restrict__ x_post, const float* __restrict__ P_post,
    const float* __restrict__ ctx,    const float* __restrict__ meas,
    const float* __restrict__ W1,     const float* __restrict__ b1,
    const float* __restrict__ W2,     const float* __restrict__ b2,
    const float* __restrict__ Hm,     const float* __restrict__ logQ,
    const float* __restrict__ logR,
    float* __restrict__ out_x, float* __restrict__ out_P)
{
    __shared__ __align__(16) float Hs[32 * H_ST];
    __shared__ __align__(16) union SU {
        struct { float W1s[64 * W1_ST]; float W2s[32 * W2_ST]; } m;  // MLP phase
        float vt[WPB][32 * V_ST];   // psl stash, then V rows; col 32 = z*d^{-1}
    } u;
    __shared__ __align__(16) float Pt[WPB][32 * P_ST];   // P_pred rows (f32)
    __shared__ float b1s[64], b2s[32], eQs[32], eRs[32];
    __shared__ float mlpbuf[WPB][64];
    __shared__ float dinvs[WPB][32];

    const int tid = threadIdx.x;
    for (int i = tid; i < 64 * 48; i += TPB) u.m.W1s[(i / 48) * W1_ST + (i % 48)] = W1[i];
    for (int i = tid; i < 32 * 64; i += TPB) u.m.W2s[(i >> 6) * W2_ST + (i & 63)] = W2[i];
    for (int i = tid; i < 32 * 32; i += TPB) Hs[(i >> 5) * H_ST + (i & 31)] = Hm[i];
    if (tid < 64) b1s[tid] = b1[tid];
    if (tid < 32) {
        b2s[tid] = b2[tid];
        eQs[tid] = expf(logQ[tid]);
        eRs[tid] = expf(logR[tid]) + 1e-6f;
    }
    __syncthreads();

    const int w    = tid >> 5;
    const int lane = tid & 31;
    const int b    = blockIdx.x * WPB + w;
    float* tP = Pt[w];
    float* tV = u.vt[w];

    // ===================== MLP (f32, noise-benign) =====================
    mlpbuf[w][lane] = x_post[(size_t)b * 32 + lane];
    if (lane < 16) mlpbuf[w][32 + lane] = ctx[(size_t)b * 16 + lane];
    __syncwarp();

    float a0 = b1s[lane], a1 = b1s[lane + 32];
#pragma unroll
    for (int j = 0; j < 48; j++) {
        float vj = mlpbuf[w][j];
        a0 = fmaf(u.m.W1s[lane * W1_ST + j], vj, a0);
        a1 = fmaf(u.m.W1s[(lane + 32) * W1_ST + j], vj, a1);
    }
    float h0 = tanhf(a0), h1 = tanhf(a1);
    __syncwarp();
    mlpbuf[w][lane]      = h0;
    mlpbuf[w][lane + 32] = h1;
    __syncwarp();

    float xp = b2s[lane];
#pragma unroll
    for (int k = 0; k < 64; k++) xp = fmaf(u.m.W2s[lane * W2_ST + k], mlpbuf[w][k], xp);
    __syncwarp();
    mlpbuf[w][lane] = xp;
    __syncwarp();

    float yv = meas[(size_t)b * 32 + lane];
#pragma unroll
    for (int j = 0; j < 32; j++) yv = fmaf(-mlpbuf[w][j], Hs[lane * H_ST + j], yv);

    // All warps done with W1/W2 before the stash/V overlay is written.
    __syncthreads();

    // ===== P_pred rows into shared =====
    {
        const float4* Pr = (const float4*)(P_post + (size_t)b * 1024 + lane * 32);
        float4* tr = (float4*)(tP + lane * P_ST);
#pragma unroll
        for (int j4 = 0; j4 < 8; j4++) tr[j4] = Pr[j4];
    }
    __syncwarp();
    tP[lane * P_ST + lane] += eQs[lane];
    __syncwarp();

    // ===== M row `lane` = H[lane][:] @ P  (packed df Dot2) =====
    u64 pmh[16], pml[16];
#pragma unroll
    for (int p = 0; p < 16; p++) { pmh[p] = 0ULL; pml[p] = 0ULL; }
#pragma unroll
    for (int k = 0; k < 32; k++) {
        float hk = Hs[lane * H_ST + k];
        u64 hk2 = pk2(hk, hk);
        const ulonglong2* pr = (const ulonglong2*)(tP + k * P_ST);
#pragma unroll
        for (int q = 0; q < 8; q++) {
            ulonglong2 two = pr[q];
            acc2p(hk2, two.x, pmh[2 * q + 0], pml[2 * q + 0]);
            acc2p(hk2, two.y, pmh[2 * q + 1], pml[2 * q + 1]);
        }
    }

    // ===== S row `lane` = M_df @ H^T + diag(eR)  (packed df) =====
    // psh kept in registers; psl STASHED to the V-tile shared region as
    // produced (register-pressure relief for 4 blocks/SM). Reloaded below.
    u64 psh[16];
    u64* stash = (u64*)(tV + lane * V_ST);   // 16 u64 per lane, 8B-aligned
    {
        float t0h = 0.f, t0l = 0.f;
#pragma unroll
        for (int k = 0; k < 32; k++) {
            const ulonglong2* hr = (const ulonglong2*)(Hs + k * H_ST);
            u64 ach = 0ULL, acl = 0ULL;
#pragma unroll
            for (int q = 0; q < 8; q++) {
                ulonglong2 two = hr[q];
                acc2dfp(pmh[2 * q + 0], pml[2 * q + 0], two.x, ach, acl);
                acc2dfp(pmh[2 * q + 1], pml[2 * q + 1], two.y, ach, acl);
            }
            // horizontal combine of the two packed halves (TwoSum)
            float a0_, a1_, c0, c1;
            upk(ach, a0_, a1_);
            upk(acl, c0, c1);
            float th = a0_ + a1_;
            float zz = th - a0_;
            float tl = ((a0_ - (th - zz)) + (a1_ - zz)) + (c0 + c1);
            if (k == lane) {   // += eR, exact TwoSum
                float eR = eRs[lane];
                float t2 = th + eR;
                float z2 = t2 - th;
                tl += (th - (t2 - z2)) + (eR - z2);
                th = t2;
            }
            if ((k & 1) == 0) { t0h = th; t0l = tl; }
            else {
                psh[k >> 1] = pk2(t0h, th);
                stash[k >> 1] = pk2(t0l, tl);   // psl -> shared
            }
        }
    }

    // RHS packs (f32): pv = f32(M) = mh + ml
    u64 pv[16];
#pragma unroll
    for (int p = 0; p < 16; p++) pv[p] = padd(pmh[p], pml[p]);

    // reload psl from stash (pmh/pml now dead)
    u64 psl[16];
#pragma unroll
    for (int p = 0; p < 16; p++) psl[p] = stash[p];

    // ===== unpivoted signed-D LDL (packed df S), f32 RHS forward-subst =====
    float myih = 0.f, myil = 0.f;
#pragma unroll
    for (int k = 0; k < 32; k++) {
        const int kp = k >> 1;
        // pivot d_k from lane k (broadcast packed, static half select)
        u64 bsh = __shfl_sync(FULL, psh[kp], k);
        u64 bsl = __shfl_sync(FULL, psl[kp], k);
        float dkh, dkl, t0, t1;
        if (k & 1) { upk(bsh, t0, dkh); upk(bsl, t1, dkl); }
        else       { upk(bsh, dkh, t0); upk(bsl, dkl, t1); }
        float ih, il; drecip(dkh, dkl, ih, il);
        if (lane == k) { myih = ih; myil = il; }
        // own s[k] (static half select)
        float skh, skl;
        if (k & 1) { upk(psh[kp], t0, skh); upk(psl[kp], t1, skl); }
        else       { upk(psh[kp], skh, t0); upk(psl[kp], skl, t1); }
        float mh_, ml_;
        dmul(skh, skl, ih, il, mh_, ml_);
        if (lane <= k) { mh_ = 0.f; ml_ = 0.f; }
        u64 pm2 = pk2(mh_, mh_), pl2 = pk2(ml_, ml_);
        float lf = mh_ + ml_;
        // S elimination on packs >= (k+1)>>1. For even k the first pack also
        // contains entry k, which is spuriously updated — it is never read
        // after this step (pivot, multiplier, archive all read before).
#pragma unroll
        for (int p = (k + 1) >> 1; p < 16; p++) {
            u64 buh = __shfl_sync(FULL, psh[p], k);
            u64 bul = __shfl_sync(FULL, psl[p], k);
            sub2p(pm2, pl2, buh, bul, psh[p], psl[p]);
        }
        // RHS forward substitution (f32, packed)
        u64 plfn = pk2(-lf, -lf);
#pragma unroll
        for (int p = 0; p < 16; p++) {
            u64 bv = __shfl_sync(FULL, pv[p], k);
            pv[p] = pfma(plfn, bv, pv[p]);
        }
        float by = __shfl_sync(FULL, yv, k);
        yv = fmaf(-lf, by, yv);
    }

    // ===== stage V rows (unscaled) + z*d^{-1}; archive d^{-1} =====
    // (overwrites the psl stash — psl already reloaded to registers)
    {
        float dinv = myih + myil;
        u64* vr = (u64*)(tV + lane * V_ST);
#pragma unroll
        for (int p = 0; p < 16; p++) vr[p] = pv[p];
        tV[lane * V_ST + 32] = yv * dinv;
        dinvs[w][lane] = dinv;
    }
    __syncwarp();

    // ===== fused x_upd & P_upd (packed rank-32 Schur update) =====
    float xo = xp;
    u64 pu[16];
    {
        const ulonglong2* pr = (const ulonglong2*)(tP + lane * P_ST);
#pragma unroll
        for (int q = 0; q < 8; q++) {
            ulonglong2 two = pr[q];
            pu[2 * q + 0] = two.x;
            pu[2 * q + 1] = two.y;
        }
    }
#pragma unroll
    for (int k = 0; k < 32; k++) {
        const float* vrk = tV + k * V_ST;
        float vt = vrk[lane];
        xo = fmaf(vt, vrk[32], xo);
        float a = vt * dinvs[w][k];
        u64 pa = pk2(-a, -a);
        const ulonglong2* vr2 = (const ulonglong2*)vrk;
#pragma unroll
        for (int q = 0; q < 8; q++) {
            ulonglong2 two = vr2[q];
            pu[2 * q + 0] = pfma(pa, two.x, pu[2 * q + 0]);
            pu[2 * q + 1] = pfma(pa, two.y, pu[2 * q + 1]);
        }
    }
    out_x[(size_t)b * 32 + lane] = xo;
    ulonglong2* Po = (ulonglong2*)(out_P + (size_t)b * 1024 + lane * 32);
#pragma unroll
    for (int q = 0; q < 8; q++)
        Po[q] = make_ulonglong2(pu[2 * q], pu[2 * q + 1]);
}

extern "C" void kernel_launch(void* const* d_in, const int* in_sizes, int n_in,
                              void* d_out, int out_size) {
    const float* x_post = (const float*)d_in[0];
    const float* P_post = (const float*)d_in[1];
    const float* ctx    = (const float*)d_in[2];
    const float* meas   = (const float*)d_in[3];
    const float* W1     = (const float*)d_in[4];
    const float* b1     = (const float*)d_in[5];
    const float* W2     = (const float*)d_in[6];
    const float* b2     = (const float*)d_in[7];
    const float* Hm     = (const float*)d_in[8];
    const float* logQ   = (const float*)d_in[9];
    const float* logR   = (const float*)d_in[10];

    float* out_x = (float*)d_out;
    float* out_P = out_x + (size_t)BATCH * 32;

    kalman_kernel<<<BATCH / WPB, TPB>>>(x_post, P_post, ctx, meas,
                                        W1, b1, W2, b2, Hm, logQ, logR,
                                        out_x, out_P);
}

// round 16
// speedup vs baseline: 17.1948x; 1.0080x over previous
#include <cuda_runtime.h>
#include <math.h>

#define BATCH 65536
#define WPB   4
#define TPB   128
#define E_ST  36
#define P_ST  36
#define V_ST  36
#define W1_ST 49
#define W2_ST 65
#define FULL  0xffffffffu

typedef unsigned long long u64;

// ---------- packed f32x2 primitives (sm_100+ PTX) ----------
__device__ __forceinline__ u64 pmul(u64 a, u64 b) {
    u64 r; asm("mul.rn.f32x2 %0,%1,%2;" : "=l"(r) : "l"(a), "l"(b)); return r;
}
__device__ __forceinline__ u64 padd(u64 a, u64 b) {
    u64 r; asm("add.rn.f32x2 %0,%1,%2;" : "=l"(r) : "l"(a), "l"(b)); return r;
}
__device__ __forceinline__ u64 psub(u64 a, u64 b) {
    u64 r; asm("sub.rn.f32x2 %0,%1,%2;" : "=l"(r) : "l"(a), "l"(b)); return r;
}
__device__ __forceinline__ u64 pfma(u64 a, u64 b, u64 c) {
    u64 r; asm("fma.rn.f32x2 %0,%1,%2,%3;" : "=l"(r) : "l"(a), "l"(b), "l"(c)); return r;
}
__device__ __forceinline__ u64 pneg(u64 a) { return a ^ 0x8000000080000000ULL; }
__device__ __forceinline__ u64 pk2(float lo, float hi) {
    u64 r; asm("mov.b64 %0, {%1,%2};" : "=l"(r) : "f"(lo), "f"(hi)); return r;
}
__device__ __forceinline__ void upk(u64 v, float& lo, float& hi) {
    asm("mov.b64 {%0,%1}, %2;" : "=f"(lo), "=f"(hi) : "l"(v));
}
// packed exact TwoSum: (s,e) = a + b
__device__ __forceinline__ void twosum(u64 a, u64 b, u64& s, u64& e) {
    s = padd(a, b);
    u64 z = psub(s, a);
    e = padd(psub(a, psub(s, z)), psub(b, z));
}
// packed: (rh,rl) -= (ah,al)*(bh,bl)
__device__ __forceinline__ void sub2p(u64 ah, u64 al, u64 bh, u64 bl,
                                      u64& rh, u64& rl) {
    u64 p = pmul(ah, bh);
    u64 e = pfma(ah, bh, pneg(p));
    e = pfma(ah, bl, e);
    e = pfma(al, bh, e);
    u64 t = psub(rh, p);
    u64 z = psub(t, rh);
    rl = padd(rl, psub(psub(psub(rh, psub(t, z)), padd(p, z)), e));
    rh = t;
}
// scalar df helpers (pivot path only)
__device__ __forceinline__ void dmul(float ah, float al, float bh, float bl,
                                     float& ph, float& pl) {
    ph = ah * bh;
    pl = fmaf(ah, bh, -ph);
    pl = fmaf(ah, bl, pl);
    pl = fmaf(al, bh, pl);
}
__device__ __forceinline__ void drecip(float dh, float dl, float& qh, float& ql) {
    float q = 1.0f / dh;
    float e = fmaf(-q, dh, 1.0f);
    e = fmaf(-q, dl, e);
    float q1 = q * e;
    float t = q + q1;
    ql = (q - t) + q1;
    qh = t;
}

__global__ void __launch_bounds__(TPB, 3) kalman_kernel(
    const float* __restrict__ x_post, const float* __restrict__ P_post,
    const float* __restrict__ ctx,    const float* __restrict__ meas,
    const float* __restrict__ W1,     const float* __restrict__ b1,
    const float* __restrict__ W2,     const float* __restrict__ b2,
    const float* __restrict__ Hm,     const float* __restrict__ logQ,
    const float* __restrict__ logR,
    float* __restrict__ out_x, float* __restrict__ out_P)
{
    // EsT[k*E_ST + j] = E[j][k] = H[j][k] - (j==k). One tile serves:
    //  - scalar reads E[t][k] = EsT[k*E_ST + t]  (conflict-free over lanes)
    //  - packed row reads EsT[k][:] for T' = P E^T
    __shared__ __align__(16) float EsT[32 * E_ST];
    __shared__ __align__(16) union SU {
        struct { float W1s[64 * W1_ST]; float W2s[32 * W2_ST]; } m;  // MLP phase
        float vt[WPB][32 * V_ST];   // T' rows, later V rows (+z*dinv at col 32)
    } u;
    __shared__ __align__(16) float Pt[WPB][32 * P_ST];   // P_pred rows (f32)
    __shared__ float b1s[64], b2s[32], eQs[32], eRs[32];
    __shared__ float mlpbuf[WPB][64];
    __shared__ float dinvs[WPB][32];

    const int tid = threadIdx.x;
    for (int i = tid; i < 64 * 48; i += TPB) u.m.W1s[(i / 48) * W1_ST + (i % 48)] = W1[i];
    for (int i = tid; i < 32 * 64; i += TPB) u.m.W2s[(i >> 6) * W2_ST + (i & 63)] = W2[i];
    for (int i = tid; i < 32 * 32; i += TPB) {
        int j = i >> 5, k = i & 31;
        EsT[k * E_ST + j] = Hm[i] - ((j == k) ? 1.0f : 0.0f);
    }
    if (tid < 64) b1s[tid] = b1[tid];
    if (tid < 32) {
        b2s[tid] = b2[tid];
        eQs[tid] = expf(logQ[tid]);
        eRs[tid] = expf(logR[tid]) + 1e-6f;
    }
    __syncthreads();

    const int w    = tid >> 5;
    const int lane = tid & 31;
    const int b    = blockIdx.x * WPB + w;
    float* tP = Pt[w];
    float* tV = u.vt[w];

    // ===================== MLP (f32, noise-benign) =====================
    mlpbuf[w][lane] = x_post[(size_t)b * 32 + lane];
    if (lane < 16) mlpbuf[w][32 + lane] = ctx[(size_t)b * 16 + lane];
    __syncwarp();

    float a0 = b1s[lane], a1 = b1s[lane + 32];
#pragma unroll
    for (int j = 0; j < 48; j++) {
        float vj = mlpbuf[w][j];
        a0 = fmaf(u.m.W1s[lane * W1_ST + j], vj, a0);
        a1 = fmaf(u.m.W1s[(lane + 32) * W1_ST + j], vj, a1);
    }
    float h0 = tanhf(a0), h1 = tanhf(a1);
    __syncwarp();
    mlpbuf[w][lane]      = h0;
    mlpbuf[w][lane + 32] = h1;
    __syncwarp();

    float xp = b2s[lane];
#pragma unroll
    for (int k = 0; k < 64; k++) xp = fmaf(u.m.W2s[lane * W2_ST + k], mlpbuf[w][k], xp);
    __syncwarp();
    mlpbuf[w][lane] = xp;
    __syncwarp();

    // y = meas - x_pred @ H^T = meas - xp_t - sum_j xp_j E[t][j]
    float yv = meas[(size_t)b * 32 + lane] - xp;
#pragma unroll
    for (int j = 0; j < 32; j++)
        yv = fmaf(-mlpbuf[w][j], EsT[j * E_ST + lane], yv);

    // All warps done with W1/W2 before the T'/V overlay is written.
    __syncthreads();

    // ===== P_pred rows into shared (with eQ diagonal) =====
    {
        const float4* Pr = (const float4*)(P_post + (size_t)b * 1024 + lane * 32);
        float4* tr = (float4*)(tP + lane * P_ST);
#pragma unroll
        for (int j4 = 0; j4 < 8; j4++) tr[j4] = Pr[j4];
    }
    __syncwarp();
    tP[lane * P_ST + lane] += eQs[lane];
    __syncwarp();

    // own P row as packs (needed for T' scalars, assembly, pv)
    u64 pP[16];
    {
        const u64* myrow = (const u64*)(tP + lane * P_ST);
#pragma unroll
        for (int p = 0; p < 16; p++) pP[p] = myrow[p];
    }

    // ===== T' row t = (P E^T)[t][:] = sum_k P[t][k] * EsT[k][:]
    //       grouped-4 accumulation (pairs via mul+fma, group sums) =====
    {
        u64 tpa[16];
#pragma unroll
        for (int p = 0; p < 16; p++) tpa[p] = 0ULL;
#pragma unroll
        for (int kg = 0; kg < 8; kg++) {
            float e0, e1_, e2_, e3_;
            upk(pP[2 * kg], e0, e1_);
            upk(pP[2 * kg + 1], e2_, e3_);
            u64 q0 = pk2(e0, e0), q1 = pk2(e1_, e1_);
            u64 q2 = pk2(e2_, e2_), q3 = pk2(e3_, e3_);
            const ulonglong2* r0 = (const ulonglong2*)(EsT + (4 * kg + 0) * E_ST);
            const ulonglong2* r1 = (const ulonglong2*)(EsT + (4 * kg + 1) * E_ST);
            const ulonglong2* r2 = (const ulonglong2*)(EsT + (4 * kg + 2) * E_ST);
            const ulonglong2* r3 = (const ulonglong2*)(EsT + (4 * kg + 3) * E_ST);
#pragma unroll
            for (int q = 0; q < 8; q++) {
                ulonglong2 A = r0[q], B = r1[q], C = r2[q], D = r3[q];
                u64 t01 = pfma(q1, B.x, pmul(q0, A.x));
                u64 t23 = pfma(q3, D.x, pmul(q2, C.x));
                tpa[2 * q] = padd(tpa[2 * q], padd(t01, t23));
                t01 = pfma(q1, B.y, pmul(q0, A.y));
                t23 = pfma(q3, D.y, pmul(q2, C.y));
                tpa[2 * q + 1] = padd(tpa[2 * q + 1], padd(t01, t23));
            }
        }
        u64* vr = (u64*)(tV + lane * V_ST);
#pragma unroll
        for (int p = 0; p < 16; p++) vr[p] = tpa[p];
    }
    __syncwarp();

    // ===== T row t = (E P)[t][:] = sum_k E[t][k] * P[k][:]  (grouped-4) =====
    u64 ta[16];
#pragma unroll
    for (int p = 0; p < 16; p++) ta[p] = 0ULL;
#pragma unroll
    for (int kg = 0; kg < 8; kg++) {
        float e0 = EsT[(4 * kg + 0) * E_ST + lane];
        float e1_ = EsT[(4 * kg + 1) * E_ST + lane];
        float e2_ = EsT[(4 * kg + 2) * E_ST + lane];
        float e3_ = EsT[(4 * kg + 3) * E_ST + lane];
        u64 q0 = pk2(e0, e0), q1 = pk2(e1_, e1_);
        u64 q2 = pk2(e2_, e2_), q3 = pk2(e3_, e3_);
        const ulonglong2* r0 = (const ulonglong2*)(tP + (4 * kg + 0) * P_ST);
        const ulonglong2* r1 = (const ulonglong2*)(tP + (4 * kg + 1) * P_ST);
        const ulonglong2* r2 = (const ulonglong2*)(tP + (4 * kg + 2) * P_ST);
        const ulonglong2* r3 = (const ulonglong2*)(tP + (4 * kg + 3) * P_ST);
#pragma unroll
        for (int q = 0; q < 8; q++) {
            ulonglong2 A = r0[q], B = r1[q], C = r2[q], D = r3[q];
            u64 t01 = pfma(q1, B.x, pmul(q0, A.x));
            u64 t23 = pfma(q3, D.x, pmul(q2, C.x));
            ta[2 * q] = padd(ta[2 * q], padd(t01, t23));
            t01 = pfma(q1, B.y, pmul(q0, A.y));
            t23 = pfma(q3, D.y, pmul(q2, C.y));
            ta[2 * q + 1] = padd(ta[2 * q + 1], padd(t01, t23));
        }
    }

    // ===== W row t = (E T')[t][:] = sum_k E[t][k] * T'[k][:]  (f32, tiny) =====
    u64 wa[16];
#pragma unroll
    for (int p = 0; p < 16; p++) wa[p] = 0ULL;
#pragma unroll
    for (int k = 0; k < 32; k++) {
        float ek = EsT[k * E_ST + lane];
        u64 ek2 = pk2(ek, ek);
        const ulonglong2* tr = (const ulonglong2*)(tV + k * V_ST);
#pragma unroll
        for (int q = 0; q < 8; q++) {
            ulonglong2 two = tr[q];
            wa[2 * q]     = pfma(ek2, two.x, wa[2 * q]);
            wa[2 * q + 1] = pfma(ek2, two.y, wa[2 * q + 1]);
        }
    }

    // ===== assembly: S = P (+) T (+) T' (+) W (+) eR-diag, exact TwoSum chain.
    //       pv = fl(P+T) = M row (f32 RHS, noise-benign). =====
    u64 psh[16], psl[16], pv[16];
    {
        float eR = eRs[lane];
        int dp = lane >> 1;
        const u64* myTp = (const u64*)(tV + lane * V_ST);
#pragma unroll
        for (int p = 0; p < 16; p++) {
            u64 a, e1, b2, e2, c, e3, d, e4;
            twosum(pP[p], ta[p], a, e1);
            pv[p] = a;
            twosum(a, myTp[p], b2, e2);
            twosum(b2, wa[p], c, e3);
            u64 dg = (p == dp) ? ((lane & 1) ? pk2(0.f, eR) : pk2(eR, 0.f)) : 0ULL;
            twosum(c, dg, d, e4);
            psh[p] = d;
            psl[p] = padd(padd(e1, e2), padd(e3, e4));
        }
    }

    // ===== unpivoted signed-D LDL (packed df S), f32 RHS forward-subst =====
    float myih = 0.f, myil = 0.f;
#pragma unroll
    for (int k = 0; k < 32; k++) {
        const int kp = k >> 1;
        u64 bsh = __shfl_sync(FULL, psh[kp], k);
        u64 bsl = __shfl_sync(FULL, psl[kp], k);
        float dkh, dkl, t0, t1;
        if (k & 1) { upk(bsh, t0, dkh); upk(bsl, t1, dkl); }
        else       { upk(bsh, dkh, t0); upk(bsl, dkl, t1); }
        float ih, il; drecip(dkh, dkl, ih, il);
        if (lane == k) { myih = ih; myil = il; }
        float skh, skl;
        if (k & 1) { upk(psh[kp], t0, skh); upk(psl[kp], t1, skl); }
        else       { upk(psh[kp], skh, t0); upk(psl[kp], skl, t1); }
        float mh_, ml_;
        dmul(skh, skl, ih, il, mh_, ml_);
        if (lane <= k) { mh_ = 0.f; ml_ = 0.f; }
        u64 pm2 = pk2(mh_, mh_), pl2 = pk2(ml_, ml_);
        float lf = mh_ + ml_;
#pragma unroll
        for (int p = (k + 1) >> 1; p < 16; p++) {
            u64 buh = __shfl_sync(FULL, psh[p], k);
            u64 bul = __shfl_sync(FULL, psl[p], k);
            sub2p(pm2, pl2, buh, bul, psh[p], psl[p]);
        }
        u64 plfn = pk2(-lf, -lf);
#pragma unroll
        for (int p = 0; p < 16; p++) {
            u64 bv = __shfl_sync(FULL, pv[p], k);
            pv[p] = pfma(plfn, bv, pv[p]);
        }
        float by = __shfl_sync(FULL, yv, k);
        yv = fmaf(-lf, by, yv);
    }

    // ===== stage V rows (unscaled) + z*d^{-1}; archive d^{-1} =====
    // (overwrites the T' staging — T' fully consumed above)
    {
        float dinv = myih + myil;
        u64* vr = (u64*)(tV + lane * V_ST);
#pragma unroll
        for (int p = 0; p < 16; p++) vr[p] = pv[p];
        tV[lane * V_ST + 32] = yv * dinv;
        dinvs[w][lane] = dinv;
    }
    __syncwarp();

    // ===== fused x_upd & P_upd (packed rank-32 Schur update) =====
    float xo = xp;
    u64 pu[16];
    {
        const ulonglong2* pr = (const ulonglong2*)(tP + lane * P_ST);
#pragma unroll
        for (int q = 0; q < 8; q++) {
            ulonglong2 two = pr[q];
            pu[2 * q + 0] = two.x;
            pu[2 * q + 1] = two.y;
        }
    }
#pragma unroll
    for (int k = 0; k < 32; k++) {
        const float* vrk = tV + k * V_ST;
        float vt = vrk[lane];
        xo = fmaf(vt, vrk[32], xo);
        float a = vt * dinvs[w][k];
        u64 pa = pk2(-a, -a);
        const ulonglong2* vr2 = (const ulonglong2*)vrk;
#pragma unroll
        for (int q = 0; q < 8; q++) {
            ulonglong2 two = vr2[q];
            pu[2 * q + 0] = pfma(pa, two.x, pu[2 * q + 0]);
            pu[2 * q + 1] = pfma(pa, two.y, pu[2 * q + 1]);
        }
    }
    out_x[(size_t)b * 32 + lane] = xo;
    ulonglong2* Po = (ulonglong2*)(out_P + (size_t)b * 1024 + lane * 32);
#pragma unroll
    for (int q = 0; q < 8; q++)
        Po[q] = make_ulonglong2(pu[2 * q], pu[2 * q + 1]);
}

extern "C" void kernel_launch(void* const* d_in, const int* in_sizes, int n_in,
                              void* d_out, int out_size) {
    const float* x_post = (const float*)d_in[0];
    const float* P_post = (const float*)d_in[1];
    const float* ctx    = (const float*)d_in[2];
    const float* meas   = (const float*)d_in[3];
    const float* W1     = (const float*)d_in[4];
    const float* b1     = (const float*)d_in[5];
    const float* W2     = (const float*)d_in[6];
    const float* b2     = (const float*)d_in[7];
    const float* Hm     = (const float*)d_in[8];
    const float* logQ   = (const float*)d_in[9];
    const float* logR   = (const float*)d_in[10];

    float* out_x = (float*)d_out;
    float* out_P = out_x + (size_t)BATCH * 32;

    kalman_kernel<<<BATCH / WPB, TPB>>>(x_post, P_post, ctx, meas,
                                        W1, b1, W2, b2, Hm, logQ, logR,
                                        out_x, out_P);
}

// round 17
// speedup vs baseline: 33.3668x; 1.9405x over previous
#include <cuda_runtime.h>
#include <math.h>

#define BATCH 65536
#define WPB   4
#define TPB   128
#define E_ST  36
#define P_ST  36
#define V_ST  36
#define W1_ST 49
#define W2_ST 65
#define FULL  0xffffffffu

typedef unsigned long long u64;

// ---------- packed f32x2 primitives (sm_100+ PTX) ----------
__device__ __forceinline__ u64 pmul(u64 a, u64 b) {
    u64 r; asm("mul.rn.f32x2 %0,%1,%2;" : "=l"(r) : "l"(a), "l"(b)); return r;
}
__device__ __forceinline__ u64 padd(u64 a, u64 b) {
    u64 r; asm("add.rn.f32x2 %0,%1,%2;" : "=l"(r) : "l"(a), "l"(b)); return r;
}
__device__ __forceinline__ u64 psub(u64 a, u64 b) {
    u64 r; asm("sub.rn.f32x2 %0,%1,%2;" : "=l"(r) : "l"(a), "l"(b)); return r;
}
__device__ __forceinline__ u64 pfma(u64 a, u64 b, u64 c) {
    u64 r; asm("fma.rn.f32x2 %0,%1,%2,%3;" : "=l"(r) : "l"(a), "l"(b), "l"(c)); return r;
}
__device__ __forceinline__ u64 pneg(u64 a) { return a ^ 0x8000000080000000ULL; }
__device__ __forceinline__ u64 pk2(float lo, float hi) {
    u64 r; asm("mov.b64 %0, {%1,%2};" : "=l"(r) : "f"(lo), "f"(hi)); return r;
}
__device__ __forceinline__ void upk(u64 v, float& lo, float& hi) {
    asm("mov.b64 {%0,%1}, %2;" : "=f"(lo), "=f"(hi) : "l"(v));
}
// packed exact TwoSum: (s,e) = a + b
__device__ __forceinline__ void twosum(u64 a, u64 b, u64& s, u64& e) {
    s = padd(a, b);
    u64 z = psub(s, a);
    e = padd(psub(a, psub(s, z)), psub(b, z));
}
// packed: (rh,rl) -= (ah,al)*(bh,bl)
__device__ __forceinline__ void sub2p(u64 ah, u64 al, u64 bh, u64 bl,
                                      u64& rh, u64& rl) {
    u64 p = pmul(ah, bh);
    u64 e = pfma(ah, bh, pneg(p));
    e = pfma(ah, bl, e);
    e = pfma(al, bh, e);
    u64 t = psub(rh, p);
    u64 z = psub(t, rh);
    rl = padd(rl, psub(psub(psub(rh, psub(t, z)), padd(p, z)), e));
    rh = t;
}
// scalar df helpers (pivot path only)
__device__ __forceinline__ void dmul(float ah, float al, float bh, float bl,
                                     float& ph, float& pl) {
    ph = ah * bh;
    pl = fmaf(ah, bh, -ph);
    pl = fmaf(ah, bl, pl);
    pl = fmaf(al, bh, pl);
}
__device__ __forceinline__ void drecip(float dh, float dl, float& qh, float& ql) {
    float q = 1.0f / dh;
    float e = fmaf(-q, dh, 1.0f);
    e = fmaf(-q, dl, e);
    float q1 = q * e;
    float t = q + q1;
    ql = (q - t) + q1;
    qh = t;
}

__global__ void __launch_bounds__(TPB, 3) kalman_kernel(
    const float* __restrict__ x_post, const float* __restrict__ P_post,
    const float* __restrict__ ctx,    const float* __restrict__ meas,
    const float* __restrict__ W1,     const float* __restrict__ b1,
    const float* __restrict__ W2,     const float* __restrict__ b2,
    const float* __restrict__ Hm,     const float* __restrict__ logQ,
    const float* __restrict__ logR,
    float* __restrict__ out_x, float* __restrict__ out_P)
{
    // EsT[k*E_ST + j] = E[j][k] = H[j][k] - (j==k).
    __shared__ __align__(16) float EsT[32 * E_ST];
    __shared__ __align__(16) union SU {
        struct { float W1s[64 * W1_ST]; float W2s[32 * W2_ST]; } m;  // MLP phase
        float vt[WPB][32 * V_ST];   // V rows (+ z*dinv at col 32) after solve
    } u;
    __shared__ __align__(16) float Pt[WPB][32 * P_ST];   // P_pred rows (f32)
    __shared__ float b1s[64], b2s[32], eQs[32], eRs[32];
    __shared__ float mlpbuf[WPB][64];
    __shared__ float dinvs[WPB][32];

    const int tid = threadIdx.x;
    for (int i = tid; i < 64 * 48; i += TPB) u.m.W1s[(i / 48) * W1_ST + (i % 48)] = W1[i];
    for (int i = tid; i < 32 * 64; i += TPB) u.m.W2s[(i >> 6) * W2_ST + (i & 63)] = W2[i];
    for (int i = tid; i < 32 * 32; i += TPB) {
        int j = i >> 5, k = i & 31;
        EsT[k * E_ST + j] = Hm[i] - ((j == k) ? 1.0f : 0.0f);
    }
    if (tid < 64) b1s[tid] = b1[tid];
    if (tid < 32) {
        b2s[tid] = b2[tid];
        eQs[tid] = expf(logQ[tid]);
        eRs[tid] = expf(logR[tid]) + 1e-6f;
    }
    __syncthreads();

    const int w    = tid >> 5;
    const int lane = tid & 31;
    const int b    = blockIdx.x * WPB + w;
    float* tP = Pt[w];
    float* tV = u.vt[w];

    // ===================== MLP (f32, noise-benign) =====================
    mlpbuf[w][lane] = x_post[(size_t)b * 32 + lane];
    if (lane < 16) mlpbuf[w][32 + lane] = ctx[(size_t)b * 16 + lane];
    __syncwarp();

    float a0 = b1s[lane], a1 = b1s[lane + 32];
#pragma unroll
    for (int j = 0; j < 48; j++) {
        float vj = mlpbuf[w][j];
        a0 = fmaf(u.m.W1s[lane * W1_ST + j], vj, a0);
        a1 = fmaf(u.m.W1s[(lane + 32) * W1_ST + j], vj, a1);
    }
    float h0 = tanhf(a0), h1 = tanhf(a1);
    __syncwarp();
    mlpbuf[w][lane]      = h0;
    mlpbuf[w][lane + 32] = h1;
    __syncwarp();

    float xp = b2s[lane];
#pragma unroll
    for (int k = 0; k < 64; k++) xp = fmaf(u.m.W2s[lane * W2_ST + k], mlpbuf[w][k], xp);
    __syncwarp();
    mlpbuf[w][lane] = xp;
    __syncwarp();

    // y = meas - x_pred @ H^T = meas - xp_t - sum_j xp_j E[t][j]
    float yv = meas[(size_t)b * 32 + lane] - xp;
#pragma unroll
    for (int j = 0; j < 32; j++)
        yv = fmaf(-mlpbuf[w][j], EsT[j * E_ST + lane], yv);

    // All warps done with W1/W2 before the V overlay is written.
    __syncthreads();

    // ===== P_pred rows into shared (with eQ diagonal) =====
    {
        const float4* Pr = (const float4*)(P_post + (size_t)b * 1024 + lane * 32);
        float4* tr = (float4*)(tP + lane * P_ST);
#pragma unroll
        for (int j4 = 0; j4 < 8; j4++) tr[j4] = Pr[j4];
    }
    __syncwarp();
    tP[lane * P_ST + lane] += eQs[lane];
    __syncwarp();

    // own P row as packs
    u64 pP[16];
    {
        const u64* myrow = (const u64*)(tP + lane * P_ST);
#pragma unroll
        for (int p = 0; p < 16; p++) pP[p] = myrow[p];
    }

    // ===== T row t = (E P)[t][:] = sum_k E[t][k] * P[k][:]  (grouped-4) =====
    u64 ta[16];
#pragma unroll
    for (int p = 0; p < 16; p++) ta[p] = 0ULL;
#pragma unroll
    for (int kg = 0; kg < 8; kg++) {
        float e0 = EsT[(4 * kg + 0) * E_ST + lane];
        float e1_ = EsT[(4 * kg + 1) * E_ST + lane];
        float e2_ = EsT[(4 * kg + 2) * E_ST + lane];
        float e3_ = EsT[(4 * kg + 3) * E_ST + lane];
        u64 q0 = pk2(e0, e0), q1 = pk2(e1_, e1_);
        u64 q2 = pk2(e2_, e2_), q3 = pk2(e3_, e3_);
        const ulonglong2* r0 = (const ulonglong2*)(tP + (4 * kg + 0) * P_ST);
        const ulonglong2* r1 = (const ulonglong2*)(tP + (4 * kg + 1) * P_ST);
        const ulonglong2* r2 = (const ulonglong2*)(tP + (4 * kg + 2) * P_ST);
        const ulonglong2* r3 = (const ulonglong2*)(tP + (4 * kg + 3) * P_ST);
#pragma unroll
        for (int q = 0; q < 8; q++) {
            ulonglong2 A = r0[q], B = r1[q], C = r2[q], D = r3[q];
            u64 t01 = pfma(q1, B.x, pmul(q0, A.x));
            u64 t23 = pfma(q3, D.x, pmul(q2, C.x));
            ta[2 * q] = padd(ta[2 * q], padd(t01, t23));
            t01 = pfma(q1, B.y, pmul(q0, A.y));
            t23 = pfma(q3, D.y, pmul(q2, C.y));
            ta[2 * q + 1] = padd(ta[2 * q + 1], padd(t01, t23));
        }
    }

    // ===== C = P (+) T  (exact packed TwoSum). ch = fl(C) = M row = RHS. =====
    u64 ch[16], cl[16];
#pragma unroll
    for (int p = 0; p < 16; p++) twosum(pP[p], ta[p], ch[p], cl[p]);

    // ===== G row t = (fl(C) E^T)[t][:] = sum_k ch_k * EsT[k][:]  (grouped-4) =====
    u64 ga[16];
#pragma unroll
    for (int p = 0; p < 16; p++) ga[p] = 0ULL;
#pragma unroll
    for (int kg = 0; kg < 8; kg++) {
        float e0, e1_, e2_, e3_;
        upk(ch[2 * kg], e0, e1_);
        upk(ch[2 * kg + 1], e2_, e3_);
        u64 q0 = pk2(e0, e0), q1 = pk2(e1_, e1_);
        u64 q2 = pk2(e2_, e2_), q3 = pk2(e3_, e3_);
        const ulonglong2* r0 = (const ulonglong2*)(EsT + (4 * kg + 0) * E_ST);
        const ulonglong2* r1 = (const ulonglong2*)(EsT + (4 * kg + 1) * E_ST);
        const ulonglong2* r2 = (const ulonglong2*)(EsT + (4 * kg + 2) * E_ST);
        const ulonglong2* r3 = (const ulonglong2*)(EsT + (4 * kg + 3) * E_ST);
#pragma unroll
        for (int q = 0; q < 8; q++) {
            ulonglong2 A = r0[q], B = r1[q], C = r2[q], D = r3[q];
            u64 t01 = pfma(q1, B.x, pmul(q0, A.x));
            u64 t23 = pfma(q3, D.x, pmul(q2, C.x));
            ga[2 * q] = padd(ga[2 * q], padd(t01, t23));
            t01 = pfma(q1, B.y, pmul(q0, A.y));
            t23 = pfma(q3, D.y, pmul(q2, C.y));
            ga[2 * q + 1] = padd(ga[2 * q + 1], padd(t01, t23));
        }
    }

    // fold eR into G's diagonal slot (f32; ~1e-8 rel on S, negligible)
    {
        float eR = eRs[lane];
        u64 dg = (lane & 1) ? pk2(0.f, eR) : pk2(eR, 0.f);
        const int dp = lane >> 1;
#pragma unroll
        for (int p = 0; p < 16; p++)
            if (p == dp) ga[p] = padd(ga[p], dg);
    }

    // ===== assembly: S = C (+) G  -> (psh, psl);  pv = ch (RHS) =====
    u64 psh[16], psl[16];
#pragma unroll
    for (int p = 0; p < 16; p++) {
        u64 s1, e1;
        twosum(ch[p], ga[p], s1, e1);
        psh[p] = s1;
        psl[p] = padd(cl[p], e1);
    }

    // ===== unpivoted signed-D LDL (packed df S), f32 RHS forward-subst =====
    float myih = 0.f, myil = 0.f;
#pragma unroll
    for (int k = 0; k < 32; k++) {
        const int kp = k >> 1;
        u64 bsh = __shfl_sync(FULL, psh[kp], k);
        u64 bsl = __shfl_sync(FULL, psl[kp], k);
        float dkh, dkl, t0, t1;
        if (k & 1) { upk(bsh, t0, dkh); upk(bsl, t1, dkl); }
        else       { upk(bsh, dkh, t0); upk(bsl, dkl, t1); }
        float ih, il; drecip(dkh, dkl, ih, il);
        if (lane == k) { myih = ih; myil = il; }
        float skh, skl;
        if (k & 1) { upk(psh[kp], t0, skh); upk(psl[kp], t1, skl); }
        else       { upk(psh[kp], skh, t0); upk(psl[kp], skl, t1); }
        float mh_, ml_;
        dmul(skh, skl, ih, il, mh_, ml_);
        if (lane <= k) { mh_ = 0.f; ml_ = 0.f; }
        u64 pm2 = pk2(mh_, mh_), pl2 = pk2(ml_, ml_);
        float lf = mh_ + ml_;
#pragma unroll
        for (int p = (k + 1) >> 1; p < 16; p++) {
            u64 buh = __shfl_sync(FULL, psh[p], k);
            u64 bul = __shfl_sync(FULL, psl[p], k);
            sub2p(pm2, pl2, buh, bul, psh[p], psl[p]);
        }
        u64 plfn = pk2(-lf, -lf);
#pragma unroll
        for (int p = 0; p < 16; p++) {
            u64 bv = __shfl_sync(FULL, ch[p], k);
            ch[p] = pfma(plfn, bv, ch[p]);
        }
        float by = __shfl_sync(FULL, yv, k);
        yv = fmaf(-lf, by, yv);
    }

    // ===== stage V rows (unscaled) + z*d^{-1}; archive d^{-1} =====
    {
        float dinv = myih + myil;
        u64* vr = (u64*)(tV + lane * V_ST);
#pragma unroll
        for (int p = 0; p < 16; p++) vr[p] = ch[p];
        tV[lane * V_ST + 32] = yv * dinv;
        dinvs[w][lane] = dinv;
    }
    __syncwarp();

    // ===== fused x_upd & P_upd (packed rank-32 Schur update) =====
    float xo = xp;
    u64 pu[16];
    {
        const ulonglong2* pr = (const ulonglong2*)(tP + lane * P_ST);
#pragma unroll
        for (int q = 0; q < 8; q++) {
            ulonglong2 two = pr[q];
            pu[2 * q + 0] = two.x;
            pu[2 * q + 1] = two.y;
        }
    }
#pragma unroll
    for (int k = 0; k < 32; k++) {
        const float* vrk = tV + k * V_ST;
        float vt = vrk[lane];
        xo = fmaf(vt, vrk[32], xo);
        float a = vt * dinvs[w][k];
        u64 pa = pk2(-a, -a);
        const ulonglong2* vr2 = (const ulonglong2*)vrk;
#pragma unroll
        for (int q = 0; q < 8; q++) {
            ulonglong2 two = vr2[q];
            pu[2 * q + 0] = pfma(pa, two.x, pu[2 * q + 0]);
            pu[2 * q + 1] = pfma(pa, two.y, pu[2 * q + 1]);
        }
    }
    out_x[(size_t)b * 32 + lane] = xo;
    ulonglong2* Po = (ulonglong2*)(out_P + (size_t)b * 1024 + lane * 32);
#pragma unroll
    for (int q = 0; q < 8; q++)
        Po[q] = make_ulonglong2(pu[2 * q], pu[2 * q + 1]);
}

extern "C" void kernel_launch(void* const* d_in, const int* in_sizes, int n_in,
                              void* d_out, int out_size) {
    const float* x_post = (const float*)d_in[0];
    const float* P_post = (const float*)d_in[1];
    const float* ctx    = (const float*)d_in[2];
    const float* meas   = (const float*)d_in[3];
    const float* W1     = (const float*)d_in[4];
    const float* b1     = (const float*)d_in[5];
    const float* W2     = (const float*)d_in[6];
    const float* b2     = (const float*)d_in[7];
    const float* Hm     = (const float*)d_in[8];
    const float* logQ   = (const float*)d_in[9];
    const float* logR   = (const float*)d_in[10];

    float* out_x = (float*)d_out;
    float* out_P = out_x + (size_t)BATCH * 32;

    kalman_kernel<<<BATCH / WPB, TPB>>>(x_post, P_post, ctx, meas,
                                        W1, b1, W2, b2, Hm, logQ, logR,
                                        out_x, out_P);
}